// round 12
// baseline (speedup 1.0000x reference)
#include <cuda_runtime.h>
#include <cuda_bf16.h>

#define L_SEQ 4096
#define DM 768
#define NH 12
#define DK 64

typedef unsigned int u32;

// ---------------------------------------------------------------------------
// Device scratch (bf16 hi/lo split arrays)
// ---------------------------------------------------------------------------
__device__ __nv_bfloat16 g_inq_h[L_SEQ * DM], g_inq_l[L_SEQ * DM];
__device__ __nv_bfloat16 g_ink_h[L_SEQ * DM], g_ink_l[L_SEQ * DM];
__device__ __nv_bfloat16 g_inv_h[L_SEQ * DM], g_inv_l[L_SEQ * DM];
__device__ __nv_bfloat16 g_wq_h[DM * DM], g_wq_l[DM * DM];
__device__ __nv_bfloat16 g_wk_h[DM * DM], g_wk_l[DM * DM];
__device__ __nv_bfloat16 g_wv_h[DM * DM], g_wv_l[DM * DM];
__device__ __nv_bfloat16 g_wo_h[DM * DM], g_wo_l[DM * DM];
__device__ __nv_bfloat16 g_qp_h[L_SEQ * DM], g_qp_l[L_SEQ * DM];
__device__ __nv_bfloat16 g_kp_h[L_SEQ * DM], g_kp_l[L_SEQ * DM];
__device__ __nv_bfloat16 g_vt_h[L_SEQ * DM], g_vt_l[L_SEQ * DM];   // [h][d][key]
__device__ __nv_bfloat16 g_att_h[L_SEQ * DM], g_att_l[L_SEQ * DM];

// ---------------------------------------------------------------------------
// Helpers
// ---------------------------------------------------------------------------
struct HL { u32 h, l; };

// split pair (x -> low half / even col, y -> high half / odd col)
__device__ __forceinline__ HL split2(float x, float y) {
    __nv_bfloat162 hb = __floats2bfloat162_rn(x, y);
    float2 hf = __bfloat1622float2(hb);
    __nv_bfloat162 lb = __floats2bfloat162_rn(x - hf.x, y - hf.y);
    HL r;
    r.h = *reinterpret_cast<u32*>(&hb);
    r.l = *reinterpret_cast<u32*>(&lb);
    return r;
}

__device__ __forceinline__ void split1(float v, __nv_bfloat16* ph, __nv_bfloat16* pl) {
    __nv_bfloat16 hb = __float2bfloat16_rn(v);
    *ph = hb;
    *pl = __float2bfloat16_rn(v - __bfloat162float(hb));
}

#define MMA_BF16(D, A, B) asm volatile( \
    "mma.sync.aligned.m16n8k16.row.col.f32.bf16.bf16.f32 " \
    "{%0,%1,%2,%3},{%4,%5,%6,%7},{%8,%9},{%0,%1,%2,%3};\n" \
    : "+f"((D)[0]), "+f"((D)[1]), "+f"((D)[2]), "+f"((D)[3]) \
    : "r"((A)[0]), "r"((A)[1]), "r"((A)[2]), "r"((A)[3]), \
      "r"((B)[0]), "r"((B)[1]))

// ---------------------------------------------------------------------------
// fp32 -> bf16 hi/lo split (elementwise)
// ---------------------------------------------------------------------------
__global__ void convert_split_kernel(const float* __restrict__ src,
                                     __nv_bfloat16* __restrict__ dh,
                                     __nv_bfloat16* __restrict__ dl, int n)
{
    int i = (blockIdx.x * blockDim.x + threadIdx.x) * 4;
    if (i >= n) return;
    float4 x = *(const float4*)(src + i);
    HL a = split2(x.x, x.y);
    HL b = split2(x.z, x.w);
    *(uint2*)(dh + i) = make_uint2(a.h, b.h);
    *(uint2*)(dl + i) = make_uint2(a.l, b.l);
}

// ---------------------------------------------------------------------------
// GEMM: C[M,768] = A[M,768] @ W^T + b, bf16-split 3-pass MMA, fp32 accum.
// BM=128, BN=128, BK=32, 256 thr (8 warps, 4x2), warp tile 32x64.
// MODE 0: fp32 out.  MODE 1: bf16 hi/lo out.  MODE 2: bf16 hi/lo, per-head
// transposed out [h][d][m] (for V).
// ---------------------------------------------------------------------------
template <int MODE>
__global__ __launch_bounds__(256, 2) void gemm_mma_kernel(
    const __nv_bfloat16* __restrict__ Ah, const __nv_bfloat16* __restrict__ Al,
    const __nv_bfloat16* __restrict__ Wh, const __nv_bfloat16* __restrict__ Wl,
    const float* __restrict__ bias,
    float* __restrict__ Cf,
    __nv_bfloat16* __restrict__ Ch, __nv_bfloat16* __restrict__ Cl)
{
    __shared__ __nv_bfloat16 AsH[128 * 40], AsL[128 * 40];
    __shared__ __nv_bfloat16 WsH[128 * 40], WsL[128 * 40];

    const int tid = threadIdx.x;
    const int lane = tid & 31;
    const int w = tid >> 5;
    const int wm = w >> 1, wn = w & 1;
    const int mb0 = wm * 32;
    const int nb0 = wn * 64;
    const int g = lane >> 2, t = lane & 3;

    const int m0 = blockIdx.y * 128;
    const int n0 = blockIdx.x * 128;

    float acc[2][8][4];
#pragma unroll
    for (int mi = 0; mi < 2; mi++)
#pragma unroll
        for (int ni = 0; ni < 8; ni++)
#pragma unroll
            for (int j = 0; j < 4; j++) acc[mi][ni][j] = 0.f;

    for (int kt = 0; kt < DM / 32; kt++) {
        __syncthreads();
        const __nv_bfloat16* aH = Ah + (size_t)m0 * DM + kt * 32;
        const __nv_bfloat16* aL = Al + (size_t)m0 * DM + kt * 32;
        const __nv_bfloat16* wH = Wh + (size_t)n0 * DM + kt * 32;
        const __nv_bfloat16* wL = Wl + (size_t)n0 * DM + kt * 32;
#pragma unroll
        for (int p = 0; p < 2; p++) {
            int f = tid + p * 256;
            int r = f >> 2;
            int c8 = (f & 3) * 8;
            *(uint4*)&AsH[r * 40 + c8] = *(const uint4*)&aH[(size_t)r * DM + c8];
            *(uint4*)&AsL[r * 40 + c8] = *(const uint4*)&aL[(size_t)r * DM + c8];
            *(uint4*)&WsH[r * 40 + c8] = *(const uint4*)&wH[(size_t)r * DM + c8];
            *(uint4*)&WsL[r * 40 + c8] = *(const uint4*)&wL[(size_t)r * DM + c8];
        }
        __syncthreads();

#pragma unroll
        for (int kk = 0; kk < 2; kk++) {
            const int k0 = kk * 16;
            u32 ah[2][4], al[2][4];
#pragma unroll
            for (int mi = 0; mi < 2; mi++) {
                const __nv_bfloat16* pH = &AsH[(mb0 + mi * 16 + g) * 40 + k0 + 2 * t];
                const __nv_bfloat16* pL = &AsL[(mb0 + mi * 16 + g) * 40 + k0 + 2 * t];
                ah[mi][0] = *(const u32*)pH;
                ah[mi][1] = *(const u32*)(pH + 8 * 40);
                ah[mi][2] = *(const u32*)(pH + 8);
                ah[mi][3] = *(const u32*)(pH + 8 * 40 + 8);
                al[mi][0] = *(const u32*)pL;
                al[mi][1] = *(const u32*)(pL + 8 * 40);
                al[mi][2] = *(const u32*)(pL + 8);
                al[mi][3] = *(const u32*)(pL + 8 * 40 + 8);
            }
#pragma unroll
            for (int ni = 0; ni < 8; ni++) {
                const __nv_bfloat16* bH = &WsH[(nb0 + ni * 8 + g) * 40 + k0 + 2 * t];
                const __nv_bfloat16* bL = &WsL[(nb0 + ni * 8 + g) * 40 + k0 + 2 * t];
                u32 bh[2] = { *(const u32*)bH, *(const u32*)(bH + 8) };
                u32 bl[2] = { *(const u32*)bL, *(const u32*)(bL + 8) };
#pragma unroll
                for (int mi = 0; mi < 2; mi++) {
                    MMA_BF16(acc[mi][ni], ah[mi], bh);
                    MMA_BF16(acc[mi][ni], ah[mi], bl);
                    MMA_BF16(acc[mi][ni], al[mi], bh);
                }
            }
        }
    }

    // Epilogue
#pragma unroll
    for (int mi = 0; mi < 2; mi++) {
#pragma unroll
        for (int ni = 0; ni < 8; ni++) {
            int mg = m0 + mb0 + mi * 16 + g;
            int ng = n0 + nb0 + ni * 8 + 2 * t;
            float b0 = bias[ng], b1 = bias[ng + 1];
            float c0 = acc[mi][ni][0] + b0, c1 = acc[mi][ni][1] + b1;
            float c2 = acc[mi][ni][2] + b0, c3 = acc[mi][ni][3] + b1;
            if (MODE == 0) {
                *(float2*)&Cf[(size_t)mg * DM + ng] = make_float2(c0, c1);
                *(float2*)&Cf[(size_t)(mg + 8) * DM + ng] = make_float2(c2, c3);
            } else if (MODE == 1) {
                HL x = split2(c0, c1);
                *(u32*)&Ch[(size_t)mg * DM + ng] = x.h;
                *(u32*)&Cl[(size_t)mg * DM + ng] = x.l;
                HL y = split2(c2, c3);
                *(u32*)&Ch[(size_t)(mg + 8) * DM + ng] = y.h;
                *(u32*)&Cl[(size_t)(mg + 8) * DM + ng] = y.l;
            } else {
                int hh = ng >> 6, dd = ng & 63;
                size_t base = (size_t)hh * (DK * L_SEQ) + (size_t)dd * L_SEQ;
                split1(c0, &Ch[base + mg], &Cl[base + mg]);
                split1(c1, &Ch[base + L_SEQ + mg], &Cl[base + L_SEQ + mg]);
                split1(c2, &Ch[base + mg + 8], &Cl[base + mg + 8]);
                split1(c3, &Ch[base + L_SEQ + mg + 8], &Cl[base + L_SEQ + mg + 8]);
            }
        }
    }
}

// ---------------------------------------------------------------------------
// Flash attention, bf16-split 3-pass MMA. Br=128 q rows, Bc=64 keys,
// 8 warps: warp w owns query rows 16w..16w+15.
// ---------------------------------------------------------------------------
#define PIT 72
#define OFF_QH 0
#define OFF_QL (128 * PIT)
#define OFF_KH (2 * 128 * PIT)
#define OFF_KL (2 * 128 * PIT + 64 * PIT)
#define OFF_VH (2 * 128 * PIT + 2 * 64 * PIT)
#define OFF_VL (2 * 128 * PIT + 3 * 64 * PIT)
#define OFF_PH (2 * 128 * PIT + 4 * 64 * PIT)
#define OFF_PL (3 * 128 * PIT + 4 * 64 * PIT)
#define FLASH_SMEM_ELEMS (4 * 128 * PIT + 4 * 64 * PIT)
#define FLASH_SMEM_BYTES (FLASH_SMEM_ELEMS * 2)

__global__ __launch_bounds__(256, 2) void flash_mma_kernel(
    const __nv_bfloat16* __restrict__ Qh_g, const __nv_bfloat16* __restrict__ Ql_g,
    const __nv_bfloat16* __restrict__ Kh_g, const __nv_bfloat16* __restrict__ Kl_g,
    const __nv_bfloat16* __restrict__ Vh_g, const __nv_bfloat16* __restrict__ Vl_g,
    __nv_bfloat16* __restrict__ Oh_g, __nv_bfloat16* __restrict__ Ol_g)
{
    extern __shared__ __nv_bfloat16 sm[];
    __nv_bfloat16* Qsh = sm + OFF_QH;
    __nv_bfloat16* Qsl = sm + OFF_QL;
    __nv_bfloat16* Ksh = sm + OFF_KH;
    __nv_bfloat16* Ksl = sm + OFF_KL;
    __nv_bfloat16* Vsh = sm + OFF_VH;
    __nv_bfloat16* Vsl = sm + OFF_VL;
    __nv_bfloat16* Psh = sm + OFF_PH;
    __nv_bfloat16* Psl = sm + OFF_PL;

    const int tid = threadIdx.x;
    const int lane = tid & 31;
    const int w = tid >> 5;
    const int mb = w * 16;
    const int g = lane >> 2, t = lane & 3;

    const int q0 = blockIdx.x * 128;
    const int h = blockIdx.y;
    const int hoff = h * DK;
    const size_t vbase = (size_t)h * DK * L_SEQ;

    // Load Q tile (128 x 64)
    {
        const __nv_bfloat16* qh = Qh_g + (size_t)q0 * DM + hoff;
        const __nv_bfloat16* ql = Ql_g + (size_t)q0 * DM + hoff;
#pragma unroll
        for (int p = 0; p < 4; p++) {
            int f = tid + p * 256;
            int r = f >> 3;
            int c8 = (f & 7) * 8;
            *(uint4*)&Qsh[r * PIT + c8] = *(const uint4*)&qh[(size_t)r * DM + c8];
            *(uint4*)&Qsl[r * PIT + c8] = *(const uint4*)&ql[(size_t)r * DM + c8];
        }
    }

    float o[8][4];
#pragma unroll
    for (int ni = 0; ni < 8; ni++)
#pragma unroll
        for (int j = 0; j < 4; j++) o[ni][j] = 0.f;
    float m0 = -1e30f, m1 = -1e30f, l0 = 0.f, l1 = 0.f;

    for (int kt = 0; kt < L_SEQ / 64; kt++) {
        const int k0 = kt * 64;
        __syncthreads();
        // Load K (64x64) and Vt (64d x 64key)
        {
            const __nv_bfloat16* kh = Kh_g + (size_t)k0 * DM + hoff;
            const __nv_bfloat16* kl = Kl_g + (size_t)k0 * DM + hoff;
            const __nv_bfloat16* vh = Vh_g + vbase + k0;
            const __nv_bfloat16* vl = Vl_g + vbase + k0;
#pragma unroll
            for (int p = 0; p < 2; p++) {
                int f = tid + p * 256;
                int r = f >> 3;
                int c8 = (f & 7) * 8;
                *(uint4*)&Ksh[r * PIT + c8] = *(const uint4*)&kh[(size_t)r * DM + c8];
                *(uint4*)&Ksl[r * PIT + c8] = *(const uint4*)&kl[(size_t)r * DM + c8];
                *(uint4*)&Vsh[r * PIT + c8] = *(const uint4*)&vh[(size_t)r * L_SEQ + c8];
                *(uint4*)&Vsl[r * PIT + c8] = *(const uint4*)&vl[(size_t)r * L_SEQ + c8];
            }
        }
        __syncthreads();

        // S = Q K^T   (16 x 64 per warp)
        float s[8][4];
#pragma unroll
        for (int ni = 0; ni < 8; ni++)
#pragma unroll
            for (int j = 0; j < 4; j++) s[ni][j] = 0.f;

#pragma unroll
        for (int kk = 0; kk < 4; kk++) {
            const int kc = kk * 16;
            u32 ah[4], al[4];
            const __nv_bfloat16* pH = &Qsh[(mb + g) * PIT + kc + 2 * t];
            const __nv_bfloat16* pL = &Qsl[(mb + g) * PIT + kc + 2 * t];
            ah[0] = *(const u32*)pH;           ah[1] = *(const u32*)(pH + 8 * PIT);
            ah[2] = *(const u32*)(pH + 8);     ah[3] = *(const u32*)(pH + 8 * PIT + 8);
            al[0] = *(const u32*)pL;           al[1] = *(const u32*)(pL + 8 * PIT);
            al[2] = *(const u32*)(pL + 8);     al[3] = *(const u32*)(pL + 8 * PIT + 8);
#pragma unroll
            for (int ni = 0; ni < 8; ni++) {
                const __nv_bfloat16* bH = &Ksh[(ni * 8 + g) * PIT + kc + 2 * t];
                const __nv_bfloat16* bL = &Ksl[(ni * 8 + g) * PIT + kc + 2 * t];
                u32 bh[2] = { *(const u32*)bH, *(const u32*)(bH + 8) };
                u32 bl[2] = { *(const u32*)bL, *(const u32*)(bL + 8) };
                MMA_BF16(s[ni], ah, bh);
                MMA_BF16(s[ni], ah, bl);
                MMA_BF16(s[ni], al, bh);
            }
        }

        // Online softmax (rows mb+g and mb+8+g), scale 1/sqrt(64)=0.125
        float rmax0 = -1e30f, rmax1 = -1e30f;
#pragma unroll
        for (int ni = 0; ni < 8; ni++) {
            s[ni][0] *= 0.125f; s[ni][1] *= 0.125f;
            s[ni][2] *= 0.125f; s[ni][3] *= 0.125f;
            rmax0 = fmaxf(rmax0, fmaxf(s[ni][0], s[ni][1]));
            rmax1 = fmaxf(rmax1, fmaxf(s[ni][2], s[ni][3]));
        }
        rmax0 = fmaxf(rmax0, __shfl_xor_sync(0xffffffffu, rmax0, 1));
        rmax0 = fmaxf(rmax0, __shfl_xor_sync(0xffffffffu, rmax0, 2));
        rmax1 = fmaxf(rmax1, __shfl_xor_sync(0xffffffffu, rmax1, 1));
        rmax1 = fmaxf(rmax1, __shfl_xor_sync(0xffffffffu, rmax1, 2));
        float mn0 = fmaxf(m0, rmax0), mn1 = fmaxf(m1, rmax1);
        float corr0 = __expf(m0 - mn0), corr1 = __expf(m1 - mn1);
        float rs0 = 0.f, rs1 = 0.f;
#pragma unroll
        for (int ni = 0; ni < 8; ni++) {
            float p0 = __expf(s[ni][0] - mn0);
            float p1 = __expf(s[ni][1] - mn0);
            float p2 = __expf(s[ni][2] - mn1);
            float p3 = __expf(s[ni][3] - mn1);
            rs0 += p0 + p1;
            rs1 += p2 + p3;
            HL x = split2(p0, p1);
            *(u32*)&Psh[(mb + g) * PIT + ni * 8 + 2 * t] = x.h;
            *(u32*)&Psl[(mb + g) * PIT + ni * 8 + 2 * t] = x.l;
            HL y = split2(p2, p3);
            *(u32*)&Psh[(mb + 8 + g) * PIT + ni * 8 + 2 * t] = y.h;
            *(u32*)&Psl[(mb + 8 + g) * PIT + ni * 8 + 2 * t] = y.l;
        }
        rs0 += __shfl_xor_sync(0xffffffffu, rs0, 1);
        rs0 += __shfl_xor_sync(0xffffffffu, rs0, 2);
        rs1 += __shfl_xor_sync(0xffffffffu, rs1, 1);
        rs1 += __shfl_xor_sync(0xffffffffu, rs1, 2);
        l0 = l0 * corr0 + rs0;
        l1 = l1 * corr1 + rs1;
        m0 = mn0; m1 = mn1;
#pragma unroll
        for (int ni = 0; ni < 8; ni++) {
            o[ni][0] *= corr0; o[ni][1] *= corr0;
            o[ni][2] *= corr1; o[ni][3] *= corr1;
        }
        __syncthreads();

        // O += P V    (16 x 64 per warp, k over 64 keys)
#pragma unroll
        for (int kk = 0; kk < 4; kk++) {
            const int kc = kk * 16;
            u32 ph[4], pl[4];
            const __nv_bfloat16* pH = &Psh[(mb + g) * PIT + kc + 2 * t];
            const __nv_bfloat16* pL = &Psl[(mb + g) * PIT + kc + 2 * t];
            ph[0] = *(const u32*)pH;           ph[1] = *(const u32*)(pH + 8 * PIT);
            ph[2] = *(const u32*)(pH + 8);     ph[3] = *(const u32*)(pH + 8 * PIT + 8);
            pl[0] = *(const u32*)pL;           pl[1] = *(const u32*)(pL + 8 * PIT);
            pl[2] = *(const u32*)(pL + 8);     pl[3] = *(const u32*)(pL + 8 * PIT + 8);
#pragma unroll
            for (int ni = 0; ni < 8; ni++) {
                const __nv_bfloat16* bH = &Vsh[(ni * 8 + g) * PIT + kc + 2 * t];
                const __nv_bfloat16* bL = &Vsl[(ni * 8 + g) * PIT + kc + 2 * t];
                u32 vh[2] = { *(const u32*)bH, *(const u32*)(bH + 8) };
                u32 vl[2] = { *(const u32*)bL, *(const u32*)(bL + 8) };
                MMA_BF16(o[ni], ph, vh);
                MMA_BF16(o[ni], ph, vl);
                MMA_BF16(o[ni], pl, vh);
            }
        }
    }

    // Epilogue: normalize + split-write att
    float inv0 = 1.f / l0, inv1 = 1.f / l1;
#pragma unroll
    for (int ni = 0; ni < 8; ni++) {
        int row = q0 + mb + g;
        int col = hoff + ni * 8 + 2 * t;
        HL x = split2(o[ni][0] * inv0, o[ni][1] * inv0);
        *(u32*)&Oh_g[(size_t)row * DM + col] = x.h;
        *(u32*)&Ol_g[(size_t)row * DM + col] = x.l;
        HL y = split2(o[ni][2] * inv1, o[ni][3] * inv1);
        *(u32*)&Oh_g[(size_t)(row + 8) * DM + col] = y.h;
        *(u32*)&Ol_g[(size_t)(row + 8) * DM + col] = y.l;
    }
}

// ---------------------------------------------------------------------------
extern "C" void kernel_launch(void* const* d_in, const int* in_sizes, int n_in,
                              void* d_out, int out_size)
{
    const float* q  = (const float*)d_in[0];
    const float* k  = (const float*)d_in[1];
    const float* v  = (const float*)d_in[2];
    const float* Wq = (const float*)d_in[3];
    const float* bq = (const float*)d_in[4];
    const float* Wk = (const float*)d_in[5];
    const float* bk = (const float*)d_in[6];
    const float* Wv = (const float*)d_in[7];
    const float* bv = (const float*)d_in[8];
    const float* Wo = (const float*)d_in[9];
    const float* bo = (const float*)d_in[10];
    float* out = (float*)d_out;

    __nv_bfloat16 *inq_h, *inq_l, *ink_h, *ink_l, *inv_h, *inv_l;
    __nv_bfloat16 *wq_h, *wq_l, *wk_h, *wk_l, *wv_h, *wv_l, *wo_h, *wo_l;
    __nv_bfloat16 *qp_h, *qp_l, *kp_h, *kp_l, *vt_h, *vt_l, *att_h, *att_l;
    cudaGetSymbolAddress((void**)&inq_h, g_inq_h); cudaGetSymbolAddress((void**)&inq_l, g_inq_l);
    cudaGetSymbolAddress((void**)&ink_h, g_ink_h); cudaGetSymbolAddress((void**)&ink_l, g_ink_l);
    cudaGetSymbolAddress((void**)&inv_h, g_inv_h); cudaGetSymbolAddress((void**)&inv_l, g_inv_l);
    cudaGetSymbolAddress((void**)&wq_h, g_wq_h);   cudaGetSymbolAddress((void**)&wq_l, g_wq_l);
    cudaGetSymbolAddress((void**)&wk_h, g_wk_h);   cudaGetSymbolAddress((void**)&wk_l, g_wk_l);
    cudaGetSymbolAddress((void**)&wv_h, g_wv_h);   cudaGetSymbolAddress((void**)&wv_l, g_wv_l);
    cudaGetSymbolAddress((void**)&wo_h, g_wo_h);   cudaGetSymbolAddress((void**)&wo_l, g_wo_l);
    cudaGetSymbolAddress((void**)&qp_h, g_qp_h);   cudaGetSymbolAddress((void**)&qp_l, g_qp_l);
    cudaGetSymbolAddress((void**)&kp_h, g_kp_h);   cudaGetSymbolAddress((void**)&kp_l, g_kp_l);
    cudaGetSymbolAddress((void**)&vt_h, g_vt_h);   cudaGetSymbolAddress((void**)&vt_l, g_vt_l);
    cudaGetSymbolAddress((void**)&att_h, g_att_h); cudaGetSymbolAddress((void**)&att_l, g_att_l);

    static bool attr_set = false;
    if (!attr_set) {
        cudaFuncSetAttribute(flash_mma_kernel,
                             cudaFuncAttributeMaxDynamicSharedMemorySize,
                             FLASH_SMEM_BYTES);
        attr_set = true;
    }

    const int nAct = L_SEQ * DM;   // 3,145,728
    const int nW = DM * DM;        // 589,824

    // 1) split inputs + weights to bf16 hi/lo
    convert_split_kernel<<<nAct / 1024, 256>>>(q, inq_h, inq_l, nAct);
    convert_split_kernel<<<nAct / 1024, 256>>>(k, ink_h, ink_l, nAct);
    convert_split_kernel<<<nAct / 1024, 256>>>(v, inv_h, inv_l, nAct);
    convert_split_kernel<<<nW / 1024, 256>>>(Wq, wq_h, wq_l, nW);
    convert_split_kernel<<<nW / 1024, 256>>>(Wk, wk_h, wk_l, nW);
    convert_split_kernel<<<nW / 1024, 256>>>(Wv, wv_h, wv_l, nW);
    convert_split_kernel<<<nW / 1024, 256>>>(Wo, wo_h, wo_l, nW);

    dim3 ggrid(DM / 128, L_SEQ / 128);   // (6, 32)

    // 2) projections (bf16 hi/lo outputs; V transposed per-head)
    gemm_mma_kernel<1><<<ggrid, 256>>>(inq_h, inq_l, wq_h, wq_l, bq, nullptr, qp_h, qp_l);
    gemm_mma_kernel<1><<<ggrid, 256>>>(ink_h, ink_l, wk_h, wk_l, bk, nullptr, kp_h, kp_l);
    gemm_mma_kernel<2><<<ggrid, 256>>>(inv_h, inv_l, wv_h, wv_l, bv, nullptr, vt_h, vt_l);

    // 3) attention
    dim3 fgrid(L_SEQ / 128, NH);
    flash_mma_kernel<<<fgrid, 256, FLASH_SMEM_BYTES>>>(
        qp_h, qp_l, kp_h, kp_l, vt_h, vt_l, att_h, att_l);

    // 4) output projection (fp32 out)
    gemm_mma_kernel<0><<<ggrid, 256>>>(att_h, att_l, wo_h, wo_l, bo, out, nullptr, nullptr);
}

// round 16
// speedup vs baseline: 1.2128x; 1.2128x over previous
#include <cuda_runtime.h>
#include <cuda_bf16.h>

#define L_SEQ 4096
#define DM 768
#define NH 12
#define DK 64

typedef unsigned int u32;

// ---------------------------------------------------------------------------
// Device scratch (bf16 hi/lo split arrays)
// ---------------------------------------------------------------------------
__device__ __nv_bfloat16 g_inq_h[L_SEQ * DM], g_inq_l[L_SEQ * DM];
__device__ __nv_bfloat16 g_ink_h[L_SEQ * DM], g_ink_l[L_SEQ * DM];
__device__ __nv_bfloat16 g_inv_h[L_SEQ * DM], g_inv_l[L_SEQ * DM];
__device__ __nv_bfloat16 g_wq_h[DM * DM], g_wq_l[DM * DM];
__device__ __nv_bfloat16 g_wk_h[DM * DM], g_wk_l[DM * DM];
__device__ __nv_bfloat16 g_wv_h[DM * DM], g_wv_l[DM * DM];
__device__ __nv_bfloat16 g_wo_h[DM * DM], g_wo_l[DM * DM];
__device__ __nv_bfloat16 g_qp_h[L_SEQ * DM], g_qp_l[L_SEQ * DM];
__device__ __nv_bfloat16 g_kp_h[L_SEQ * DM], g_kp_l[L_SEQ * DM];
__device__ __nv_bfloat16 g_vt_h[L_SEQ * DM], g_vt_l[L_SEQ * DM];   // [h][d][key]
__device__ __nv_bfloat16 g_att_h[L_SEQ * DM], g_att_l[L_SEQ * DM];

// ---------------------------------------------------------------------------
// Helpers
// ---------------------------------------------------------------------------
struct HL { u32 h, l; };

__device__ __forceinline__ HL split2(float x, float y) {
    __nv_bfloat162 hb = __floats2bfloat162_rn(x, y);
    float2 hf = __bfloat1622float2(hb);
    __nv_bfloat162 lb = __floats2bfloat162_rn(x - hf.x, y - hf.y);
    HL r;
    r.h = *reinterpret_cast<u32*>(&hb);
    r.l = *reinterpret_cast<u32*>(&lb);
    return r;
}

__device__ __forceinline__ void split1(float v, __nv_bfloat16* ph, __nv_bfloat16* pl) {
    __nv_bfloat16 hb = __float2bfloat16_rn(v);
    *ph = hb;
    *pl = __float2bfloat16_rn(v - __bfloat162float(hb));
}

__device__ __forceinline__ float ex2f(float x) {
    float y;
    asm("ex2.approx.ftz.f32 %0, %1;\n" : "=f"(y) : "f"(x));
    return y;
}

#define MMA_BF16(D, A, B) asm volatile( \
    "mma.sync.aligned.m16n8k16.row.col.f32.bf16.bf16.f32 " \
    "{%0,%1,%2,%3},{%4,%5,%6,%7},{%8,%9},{%0,%1,%2,%3};\n" \
    : "+f"((D)[0]), "+f"((D)[1]), "+f"((D)[2]), "+f"((D)[3]) \
    : "r"((A)[0]), "r"((A)[1]), "r"((A)[2]), "r"((A)[3]), \
      "r"((B)[0]), "r"((B)[1]))

__device__ __forceinline__ void ldsm4(u32* r, u32 addr) {
    asm volatile("ldmatrix.sync.aligned.m8n8.x4.shared.b16 {%0,%1,%2,%3},[%4];\n"
                 : "=r"(r[0]), "=r"(r[1]), "=r"(r[2]), "=r"(r[3]) : "r"(addr));
}

__device__ __forceinline__ void cp16(u32 dst, const void* src) {
    asm volatile("cp.async.cg.shared.global [%0],[%1],16;\n" :: "r"(dst), "l"(src));
}
#define CP_COMMIT() asm volatile("cp.async.commit_group;\n")
#define CP_WAIT0()  asm volatile("cp.async.wait_group 0;\n")

#define SCALE_Q (0.125f * 1.4426950408889634f)   // 1/sqrt(64) * log2(e)

// ---------------------------------------------------------------------------
// fp32 -> bf16 hi/lo split (elementwise)
// ---------------------------------------------------------------------------
__global__ void convert_split_kernel(const float* __restrict__ src,
                                     __nv_bfloat16* __restrict__ dh,
                                     __nv_bfloat16* __restrict__ dl, int n)
{
    int i = (blockIdx.x * blockDim.x + threadIdx.x) * 4;
    if (i >= n) return;
    float4 x = *(const float4*)(src + i);
    HL a = split2(x.x, x.y);
    HL b = split2(x.z, x.w);
    *(uint2*)(dh + i) = make_uint2(a.h, b.h);
    *(uint2*)(dl + i) = make_uint2(a.l, b.l);
}

// ---------------------------------------------------------------------------
// GEMM: C[M,768] = (A[M,768] @ W^T + b) * scale, bf16-split 3-pass MMA.
// BM=128, BN=128, BK=32, 256 thr (8 warps 4x2), warp tile 32x64.
// cp.async double-buffered smem, ldmatrix fragment loads.
// MODE 0: fp32 out. MODE 1: bf16 hi/lo out. MODE 2: bf16 hi/lo per-head
// transposed [h][d][m] out (for V).
// ---------------------------------------------------------------------------
#define G_PIT 40
#define G_TILE (128 * G_PIT)                 // elems per sub-tile
#define G_STAGE (4 * G_TILE)                 // AH, AL, WH, WL
#define GEMM_SMEM_BYTES (2 * G_STAGE * 2)    // 81,920 B

template <int MODE>
__global__ __launch_bounds__(256, 2) void gemm_mma_kernel(
    const __nv_bfloat16* __restrict__ Ah, const __nv_bfloat16* __restrict__ Al,
    const __nv_bfloat16* __restrict__ Wh, const __nv_bfloat16* __restrict__ Wl,
    const float* __restrict__ bias, float scale,
    float* __restrict__ Cf,
    __nv_bfloat16* __restrict__ Ch, __nv_bfloat16* __restrict__ Cl)
{
    extern __shared__ __nv_bfloat16 gsm[];
    const u32 sb = (u32)__cvta_generic_to_shared(gsm);

    const int tid = threadIdx.x;
    const int lane = tid & 31;
    const int w = tid >> 5;
    const int wm = w >> 1, wn = w & 1;
    const int mb0 = wm * 32;
    const int nb0 = wn * 64;
    const int g = lane >> 2, t = lane & 3;

    const int m0 = blockIdx.y * 128;
    const int n0 = blockIdx.x * 128;

    // ldmatrix lane constants
    const int lm = lane >> 3, lr = lane & 7;
    const int a_row = (lm & 1) * 8 + lr;   // A-fragment pattern
    const int a_colb = (lm >> 1) * 16;
    const int b_row = (lm >> 1) * 8 + lr;  // B-fragment pattern
    const int b_colb = (lm & 1) * 16;

    const u32 stage_b = G_STAGE * 2;
    const u32 tile_b = G_TILE * 2;

    auto load_stage = [&](int kt, int st) {
        const __nv_bfloat16* aH = Ah + (size_t)m0 * DM + kt * 32;
        const __nv_bfloat16* aL = Al + (size_t)m0 * DM + kt * 32;
        const __nv_bfloat16* wH = Wh + (size_t)n0 * DM + kt * 32;
        const __nv_bfloat16* wL = Wl + (size_t)n0 * DM + kt * 32;
        const u32 base = sb + st * stage_b;
#pragma unroll
        for (int p = 0; p < 2; p++) {
            int f = tid + p * 256;           // 0..511
            int r = f >> 2;                  // 0..127
            int c8 = (f & 3) * 8;            // elem offset within 32
            u32 so = base + (u32)(r * G_PIT + c8) * 2;
            cp16(so,              aH + (size_t)r * DM + c8);
            cp16(so + tile_b,     aL + (size_t)r * DM + c8);
            cp16(so + 2 * tile_b, wH + (size_t)r * DM + c8);
            cp16(so + 3 * tile_b, wL + (size_t)r * DM + c8);
        }
    };

    float acc[2][8][4];
#pragma unroll
    for (int mi = 0; mi < 2; mi++)
#pragma unroll
        for (int ni = 0; ni < 8; ni++)
#pragma unroll
            for (int j = 0; j < 4; j++) acc[mi][ni][j] = 0.f;

    load_stage(0, 0);
    CP_COMMIT();

    const int NKT = DM / 32;   // 24
    for (int kt = 0; kt < NKT; kt++) {
        CP_WAIT0();
        __syncthreads();
        if (kt + 1 < NKT) { load_stage(kt + 1, (kt + 1) & 1); CP_COMMIT(); }

        const u32 stg = sb + (kt & 1) * stage_b;
#pragma unroll
        for (int kk = 0; kk < 2; kk++) {
            const int k0 = kk * 16;
            u32 ah[2][4], al[2][4];
#pragma unroll
            for (int mi = 0; mi < 2; mi++) {
                u32 aro = stg + (u32)((mb0 + mi * 16 + a_row) * G_PIT + k0) * 2 + a_colb;
                ldsm4(ah[mi], aro);
                ldsm4(al[mi], aro + tile_b);
            }
#pragma unroll
            for (int nj = 0; nj < 4; nj++) {
                u32 wro = stg + 2 * tile_b +
                          (u32)((nb0 + nj * 16 + b_row) * G_PIT + k0) * 2 + b_colb;
                u32 bh[4], bl[4];
                ldsm4(bh, wro);
                ldsm4(bl, wro + tile_b);
#pragma unroll
                for (int mi = 0; mi < 2; mi++) {
                    MMA_BF16(acc[mi][2 * nj], ah[mi], bh);
                    MMA_BF16(acc[mi][2 * nj], ah[mi], bl);
                    MMA_BF16(acc[mi][2 * nj], al[mi], bh);
                    MMA_BF16(acc[mi][2 * nj + 1], ah[mi], bh + 2);
                    MMA_BF16(acc[mi][2 * nj + 1], ah[mi], bl + 2);
                    MMA_BF16(acc[mi][2 * nj + 1], al[mi], bh + 2);
                }
            }
        }
    }

    // Epilogue
#pragma unroll
    for (int mi = 0; mi < 2; mi++) {
#pragma unroll
        for (int ni = 0; ni < 8; ni++) {
            int mg = m0 + mb0 + mi * 16 + g;
            int ng = n0 + nb0 + ni * 8 + 2 * t;
            float b0 = bias[ng], b1 = bias[ng + 1];
            float c0 = (acc[mi][ni][0] + b0) * scale, c1 = (acc[mi][ni][1] + b1) * scale;
            float c2 = (acc[mi][ni][2] + b0) * scale, c3 = (acc[mi][ni][3] + b1) * scale;
            if (MODE == 0) {
                *(float2*)&Cf[(size_t)mg * DM + ng] = make_float2(c0, c1);
                *(float2*)&Cf[(size_t)(mg + 8) * DM + ng] = make_float2(c2, c3);
            } else if (MODE == 1) {
                HL x = split2(c0, c1);
                *(u32*)&Ch[(size_t)mg * DM + ng] = x.h;
                *(u32*)&Cl[(size_t)mg * DM + ng] = x.l;
                HL y = split2(c2, c3);
                *(u32*)&Ch[(size_t)(mg + 8) * DM + ng] = y.h;
                *(u32*)&Cl[(size_t)(mg + 8) * DM + ng] = y.l;
            } else {
                int hh = ng >> 6, dd = ng & 63;
                size_t base = (size_t)hh * (DK * L_SEQ) + (size_t)dd * L_SEQ;
                split1(c0, &Ch[base + mg], &Cl[base + mg]);
                split1(c1, &Ch[base + L_SEQ + mg], &Cl[base + L_SEQ + mg]);
                split1(c2, &Ch[base + mg + 8], &Cl[base + mg + 8]);
                split1(c3, &Ch[base + L_SEQ + mg + 8], &Cl[base + L_SEQ + mg + 8]);
            }
        }
    }
}

// ---------------------------------------------------------------------------
// Flash attention, bf16-split 3-pass MMA. Br=128, Bc=64, 8 warps x 16 rows.
// Register-resident P, ldmatrix fragments, cp.async double-buffered K/V,
// exp2-domain softmax (scale*log2e folded into Q projection).
// ---------------------------------------------------------------------------
#define PIT 72
#define Q_ELEMS (128 * PIT)
#define KV_TILE (64 * PIT)
#define KV_TILE_B (KV_TILE * 2)
#define BUF_B (4 * KV_TILE_B)
#define OFF_BUF_B (2 * Q_ELEMS * 2)
#define FLASH_SMEM_BYTES (2 * Q_ELEMS * 2 + 2 * BUF_B)   // 110,592 B

__global__ __launch_bounds__(256, 2) void flash_mma_kernel(
    const __nv_bfloat16* __restrict__ Qh_g, const __nv_bfloat16* __restrict__ Ql_g,
    const __nv_bfloat16* __restrict__ Kh_g, const __nv_bfloat16* __restrict__ Kl_g,
    const __nv_bfloat16* __restrict__ Vh_g, const __nv_bfloat16* __restrict__ Vl_g,
    __nv_bfloat16* __restrict__ Oh_g, __nv_bfloat16* __restrict__ Ol_g)
{
    extern __shared__ __nv_bfloat16 sm[];
    const u32 sb = (u32)__cvta_generic_to_shared(sm);

    const int tid = threadIdx.x;
    const int lane = tid & 31;
    const int w = tid >> 5;
    const int mb = w * 16;
    const int g = lane >> 2, t = lane & 3;

    const int q0 = blockIdx.x * 128;
    const int h = blockIdx.y;
    const int hoff = h * DK;
    const size_t vbase = (size_t)h * DK * L_SEQ;

    // ldmatrix lane constants
    const int lm = lane >> 3, lr = lane & 7;
    const int a_row = (lm & 1) * 8 + lr;
    const int a_colb = (lm >> 1) * 16;
    const int b_row = (lm >> 1) * 8 + lr;
    const int b_colb = (lm & 1) * 16;

    // Q fragment base addresses (per-kk stride = 16 elems = 32 B)
    const u32 qh_base = sb + (u32)((mb + a_row) * PIT) * 2 + a_colb;
    const u32 ql_base = qh_base + Q_ELEMS * 2;

    // Load Q tile (128 x 64) hi/lo
    {
        const __nv_bfloat16* qh = Qh_g + (size_t)q0 * DM + hoff;
        const __nv_bfloat16* ql = Ql_g + (size_t)q0 * DM + hoff;
#pragma unroll
        for (int p = 0; p < 4; p++) {
            int f = tid + p * 256;
            int r = f >> 3;
            int c8 = (f & 7) * 8;
            *(uint4*)&sm[r * PIT + c8] = *(const uint4*)&qh[(size_t)r * DM + c8];
            *(uint4*)&sm[Q_ELEMS + r * PIT + c8] = *(const uint4*)&ql[(size_t)r * DM + c8];
        }
    }

    auto load_kv = [&](int kt, int bi) {
        const int k0 = kt * 64;
        const __nv_bfloat16* kh = Kh_g + (size_t)k0 * DM + hoff;
        const __nv_bfloat16* kl = Kl_g + (size_t)k0 * DM + hoff;
        const __nv_bfloat16* vh = Vh_g + vbase + k0;
        const __nv_bfloat16* vl = Vl_g + vbase + k0;
        const u32 base = sb + OFF_BUF_B + bi * BUF_B;
#pragma unroll
        for (int p = 0; p < 2; p++) {
            int f = tid + p * 256;           // 0..511
            int r = f >> 3;                  // 0..63
            int c8 = (f & 7) * 8;            // 0..56
            u32 so = base + (u32)(r * PIT + c8) * 2;
            cp16(so,                 kh + (size_t)r * DM + c8);
            cp16(so + KV_TILE_B,     kl + (size_t)r * DM + c8);
            cp16(so + 2 * KV_TILE_B, vh + (size_t)r * L_SEQ + c8);
            cp16(so + 3 * KV_TILE_B, vl + (size_t)r * L_SEQ + c8);
        }
    };

    float o[8][4];
#pragma unroll
    for (int ni = 0; ni < 8; ni++)
#pragma unroll
        for (int j = 0; j < 4; j++) o[ni][j] = 0.f;
    float m0 = -1e30f, m1 = -1e30f, l0 = 0.f, l1 = 0.f;

    load_kv(0, 0);
    CP_COMMIT();

    const int NKT = L_SEQ / 64;   // 64
    for (int kt = 0; kt < NKT; kt++) {
        CP_WAIT0();
        __syncthreads();
        if (kt + 1 < NKT) { load_kv(kt + 1, (kt + 1) & 1); CP_COMMIT(); }

        const u32 kb = sb + OFF_BUF_B + (kt & 1) * BUF_B;

        // ---- S = Q K^T (16 x 64 per warp, values in log2 domain) ----
        float s[8][4];
#pragma unroll
        for (int ni = 0; ni < 8; ni++)
#pragma unroll
            for (int j = 0; j < 4; j++) s[ni][j] = 0.f;

#pragma unroll
        for (int kk = 0; kk < 4; kk++) {
            u32 aqh[4], aql[4];
            ldsm4(aqh, qh_base + kk * 32);
            ldsm4(aql, ql_base + kk * 32);
#pragma unroll
            for (int nj = 0; nj < 4; nj++) {
                u32 kro = kb + (u32)((nj * 16 + b_row) * PIT) * 2 + kk * 32 + b_colb;
                u32 bh[4], bl[4];
                ldsm4(bh, kro);
                ldsm4(bl, kro + KV_TILE_B);
                MMA_BF16(s[2 * nj], aqh, bh);
                MMA_BF16(s[2 * nj], aqh, bl);
                MMA_BF16(s[2 * nj], aql, bh);
                MMA_BF16(s[2 * nj + 1], aqh, bh + 2);
                MMA_BF16(s[2 * nj + 1], aqh, bl + 2);
                MMA_BF16(s[2 * nj + 1], aql, bh + 2);
            }
        }

        // ---- Online softmax (exp2 domain; rows g and g+8 of warp tile) ----
        float rmax0 = -1e30f, rmax1 = -1e30f;
#pragma unroll
        for (int ni = 0; ni < 8; ni++) {
            rmax0 = fmaxf(rmax0, fmaxf(s[ni][0], s[ni][1]));
            rmax1 = fmaxf(rmax1, fmaxf(s[ni][2], s[ni][3]));
        }
        rmax0 = fmaxf(rmax0, __shfl_xor_sync(0xffffffffu, rmax0, 1));
        rmax0 = fmaxf(rmax0, __shfl_xor_sync(0xffffffffu, rmax0, 2));
        rmax1 = fmaxf(rmax1, __shfl_xor_sync(0xffffffffu, rmax1, 1));
        rmax1 = fmaxf(rmax1, __shfl_xor_sync(0xffffffffu, rmax1, 2));
        float mn0 = fmaxf(m0, rmax0), mn1 = fmaxf(m1, rmax1);
        float corr0 = ex2f(m0 - mn0), corr1 = ex2f(m1 - mn1);
        float rs0 = 0.f, rs1 = 0.f;
#pragma unroll
        for (int ni = 0; ni < 8; ni++) {
            s[ni][0] = ex2f(s[ni][0] - mn0);
            s[ni][1] = ex2f(s[ni][1] - mn0);
            s[ni][2] = ex2f(s[ni][2] - mn1);
            s[ni][3] = ex2f(s[ni][3] - mn1);
            rs0 += s[ni][0] + s[ni][1];
            rs1 += s[ni][2] + s[ni][3];
        }
        rs0 += __shfl_xor_sync(0xffffffffu, rs0, 1);
        rs0 += __shfl_xor_sync(0xffffffffu, rs0, 2);
        rs1 += __shfl_xor_sync(0xffffffffu, rs1, 1);
        rs1 += __shfl_xor_sync(0xffffffffu, rs1, 2);
        l0 = l0 * corr0 + rs0;
        l1 = l1 * corr1 + rs1;
        m0 = mn0; m1 = mn1;
#pragma unroll
        for (int ni = 0; ni < 8; ni++) {
            o[ni][0] *= corr0; o[ni][1] *= corr0;
            o[ni][2] *= corr1; o[ni][3] *= corr1;
        }

        // ---- O += P V (P hi/lo built in registers from s) ----
#pragma unroll
        for (int kk = 0; kk < 4; kk++) {
            u32 ph[4], pl[4];
            HL x0 = split2(s[2 * kk][0], s[2 * kk][1]);
            HL x1 = split2(s[2 * kk][2], s[2 * kk][3]);
            HL x2 = split2(s[2 * kk + 1][0], s[2 * kk + 1][1]);
            HL x3 = split2(s[2 * kk + 1][2], s[2 * kk + 1][3]);
            ph[0] = x0.h; ph[1] = x1.h; ph[2] = x2.h; ph[3] = x3.h;
            pl[0] = x0.l; pl[1] = x1.l; pl[2] = x2.l; pl[3] = x3.l;
#pragma unroll
            for (int nj = 0; nj < 4; nj++) {
                u32 vro = kb + 2 * KV_TILE_B +
                          (u32)((nj * 16 + b_row) * PIT) * 2 + kk * 32 + b_colb;
                u32 vh4[4], vl4[4];
                ldsm4(vh4, vro);
                ldsm4(vl4, vro + KV_TILE_B);
                MMA_BF16(o[2 * nj], ph, vh4);
                MMA_BF16(o[2 * nj], ph, vl4);
                MMA_BF16(o[2 * nj], pl, vh4);
                MMA_BF16(o[2 * nj + 1], ph, vh4 + 2);
                MMA_BF16(o[2 * nj + 1], ph, vl4 + 2);
                MMA_BF16(o[2 * nj + 1], pl, vh4 + 2);
            }
        }
    }

    // Epilogue: normalize + split-write att
    float inv0 = 1.f / l0, inv1 = 1.f / l1;
#pragma unroll
    for (int ni = 0; ni < 8; ni++) {
        int row = q0 + mb + g;
        int col = hoff + ni * 8 + 2 * t;
        HL x = split2(o[ni][0] * inv0, o[ni][1] * inv0);
        *(u32*)&Oh_g[(size_t)row * DM + col] = x.h;
        *(u32*)&Ol_g[(size_t)row * DM + col] = x.l;
        HL y = split2(o[ni][2] * inv1, o[ni][3] * inv1);
        *(u32*)&Oh_g[(size_t)(row + 8) * DM + col] = y.h;
        *(u32*)&Ol_g[(size_t)(row + 8) * DM + col] = y.l;
    }
}

// ---------------------------------------------------------------------------
extern "C" void kernel_launch(void* const* d_in, const int* in_sizes, int n_in,
                              void* d_out, int out_size)
{
    const float* q  = (const float*)d_in[0];
    const float* k  = (const float*)d_in[1];
    const float* v  = (const float*)d_in[2];
    const float* Wq = (const float*)d_in[3];
    const float* bq = (const float*)d_in[4];
    const float* Wk = (const float*)d_in[5];
    const float* bk = (const float*)d_in[6];
    const float* Wv = (const float*)d_in[7];
    const float* bv = (const float*)d_in[8];
    const float* Wo = (const float*)d_in[9];
    const float* bo = (const float*)d_in[10];
    float* out = (float*)d_out;

    __nv_bfloat16 *inq_h, *inq_l, *ink_h, *ink_l, *inv_h, *inv_l;
    __nv_bfloat16 *wq_h, *wq_l, *wk_h, *wk_l, *wv_h, *wv_l, *wo_h, *wo_l;
    __nv_bfloat16 *qp_h, *qp_l, *kp_h, *kp_l, *vt_h, *vt_l, *att_h, *att_l;
    cudaGetSymbolAddress((void**)&inq_h, g_inq_h); cudaGetSymbolAddress((void**)&inq_l, g_inq_l);
    cudaGetSymbolAddress((void**)&ink_h, g_ink_h); cudaGetSymbolAddress((void**)&ink_l, g_ink_l);
    cudaGetSymbolAddress((void**)&inv_h, g_inv_h); cudaGetSymbolAddress((void**)&inv_l, g_inv_l);
    cudaGetSymbolAddress((void**)&wq_h, g_wq_h);   cudaGetSymbolAddress((void**)&wq_l, g_wq_l);
    cudaGetSymbolAddress((void**)&wk_h, g_wk_h);   cudaGetSymbolAddress((void**)&wk_l, g_wk_l);
    cudaGetSymbolAddress((void**)&wv_h, g_wv_h);   cudaGetSymbolAddress((void**)&wv_l, g_wv_l);
    cudaGetSymbolAddress((void**)&wo_h, g_wo_h);   cudaGetSymbolAddress((void**)&wo_l, g_wo_l);
    cudaGetSymbolAddress((void**)&qp_h, g_qp_h);   cudaGetSymbolAddress((void**)&qp_l, g_qp_l);
    cudaGetSymbolAddress((void**)&kp_h, g_kp_h);   cudaGetSymbolAddress((void**)&kp_l, g_kp_l);
    cudaGetSymbolAddress((void**)&vt_h, g_vt_h);   cudaGetSymbolAddress((void**)&vt_l, g_vt_l);
    cudaGetSymbolAddress((void**)&att_h, g_att_h); cudaGetSymbolAddress((void**)&att_l, g_att_l);

    static bool attr_set = false;
    if (!attr_set) {
        cudaFuncSetAttribute(flash_mma_kernel,
                             cudaFuncAttributeMaxDynamicSharedMemorySize,
                             FLASH_SMEM_BYTES);
        cudaFuncSetAttribute(gemm_mma_kernel<0>,
                             cudaFuncAttributeMaxDynamicSharedMemorySize,
                             GEMM_SMEM_BYTES);
        cudaFuncSetAttribute(gemm_mma_kernel<1>,
                             cudaFuncAttributeMaxDynamicSharedMemorySize,
                             GEMM_SMEM_BYTES);
        cudaFuncSetAttribute(gemm_mma_kernel<2>,
                             cudaFuncAttributeMaxDynamicSharedMemorySize,
                             GEMM_SMEM_BYTES);
        attr_set = true;
    }

    const int nAct = L_SEQ * DM;   // 3,145,728
    const int nW = DM * DM;        // 589,824

    // 1) split inputs + weights to bf16 hi/lo
    convert_split_kernel<<<nAct / 1024, 256>>>(q, inq_h, inq_l, nAct);
    convert_split_kernel<<<nAct / 1024, 256>>>(k, ink_h, ink_l, nAct);
    convert_split_kernel<<<nAct / 1024, 256>>>(v, inv_h, inv_l, nAct);
    convert_split_kernel<<<nW / 1024, 256>>>(Wq, wq_h, wq_l, nW);
    convert_split_kernel<<<nW / 1024, 256>>>(Wk, wk_h, wk_l, nW);
    convert_split_kernel<<<nW / 1024, 256>>>(Wv, wv_h, wv_l, nW);
    convert_split_kernel<<<nW / 1024, 256>>>(Wo, wo_h, wo_l, nW);

    dim3 ggrid(DM / 128, L_SEQ / 128);   // (6, 32)

    // 2) projections; Q gets scale*log2e folded in, V emitted transposed
    gemm_mma_kernel<1><<<ggrid, 256, GEMM_SMEM_BYTES>>>(
        inq_h, inq_l, wq_h, wq_l, bq, SCALE_Q, nullptr, qp_h, qp_l);
    gemm_mma_kernel<1><<<ggrid, 256, GEMM_SMEM_BYTES>>>(
        ink_h, ink_l, wk_h, wk_l, bk, 1.0f, nullptr, kp_h, kp_l);
    gemm_mma_kernel<2><<<ggrid, 256, GEMM_SMEM_BYTES>>>(
        inv_h, inv_l, wv_h, wv_l, bv, 1.0f, nullptr, vt_h, vt_l);

    // 3) attention
    dim3 fgrid(L_SEQ / 128, NH);
    flash_mma_kernel<<<fgrid, 256, FLASH_SMEM_BYTES>>>(
        qp_h, qp_l, kp_h, kp_l, vt_h, vt_l, att_h, att_l);

    // 4) output projection (fp32 out)
    gemm_mma_kernel<0><<<ggrid, 256, GEMM_SMEM_BYTES>>>(
        att_h, att_l, wo_h, wo_l, bo, 1.0f, out, nullptr, nullptr);
}